// round 1
// baseline (speedup 1.0000x reference)
#include <cuda_runtime.h>
#include <cstddef>

// Problem dims
#define NB 16384          // batch
#define DD 1024           // hidden
#define HD 2048           // heads*hidden for gat1 output

// ---------------------------------------------------------------------------
// Static scratch (device globals -- allocation APIs are forbidden)
// ---------------------------------------------------------------------------
__device__ float g_Xa[(size_t)NB * DD];     // relu(LN(audio proj))      64MB
__device__ float g_Xt[(size_t)NB * DD];     // relu(LN(text proj))       64MB
__device__ float g_Za[(size_t)NB * HD];     // gat1 pre-act (audio)     128MB (also proj temp)
__device__ float g_Zt[(size_t)NB * HD];     // gat1 pre-act (text)      128MB (also proj temp)
__device__ float g_H [(size_t)NB * HD];     // averaged relu'd gat1     128MB
__device__ float g_W2T[(size_t)HD * DD];    // W2 transposed              8MB
__device__ float g_Wc [(size_t)DD * HD];    // Wf @ W2                    8MB
__device__ float g_bc [DD];                 // Wf @ b2 + bf
__device__ float g_xp2[2 * DD];             // gat2 xp for nodes 0,1

__device__ __forceinline__ float lrelu_f(float v) { return v > 0.f ? v : 0.2f * v; }

// ---------------------------------------------------------------------------
// SGEMM: C[M,N] = A[M,K] * B[N,K]^T   (all row-major; M,N multiples of 128,
// K multiple of 8). 128x128 tile, BK=8, 256 threads, 8x8 microtile,
// double-buffered shared memory.
// ---------------------------------------------------------------------------
__global__ void __launch_bounds__(256) sgemm_nt(
    const float* __restrict__ A, const float* __restrict__ B,
    float* __restrict__ C, int M, int N, int K)
{
    __shared__ float As[2][8][128];
    __shared__ float Bs[2][8][128];

    const int tid = threadIdx.x;
    const int bm  = blockIdx.y * 128;
    const int bn  = blockIdx.x * 128;

    // loading map: thread t -> row t/2, k-quad (t&1)*4
    const int lrow = tid >> 1;
    const int lk   = (tid & 1) << 2;
    const float* Ap = A + (size_t)(bm + lrow) * K + lk;
    const float* Bp = B + (size_t)(bn + lrow) * K + lk;

    // compute map: 8 warps as 4(M) x 2(N); lanes as 4(M) x 8(N); each 8x8
    const int w = tid >> 5, l = tid & 31;
    const int tm = (w & 3) * 32 + (l >> 3) * 8;
    const int tn = (w >> 2) * 64 + (l & 7) * 8;

    float acc[8][8];
#pragma unroll
    for (int i = 0; i < 8; i++)
#pragma unroll
        for (int j = 0; j < 8; j++) acc[i][j] = 0.f;

    // prologue: tile 0
    float4 a4 = *(const float4*)Ap;
    float4 b4 = *(const float4*)Bp;
    As[0][lk+0][lrow] = a4.x; As[0][lk+1][lrow] = a4.y;
    As[0][lk+2][lrow] = a4.z; As[0][lk+3][lrow] = a4.w;
    Bs[0][lk+0][lrow] = b4.x; Bs[0][lk+1][lrow] = b4.y;
    Bs[0][lk+2][lrow] = b4.z; Bs[0][lk+3][lrow] = b4.w;
    __syncthreads();

    const int nk = K >> 3;
    int buf = 0;
    for (int t = 0; t < nk; t++) {
        if (t + 1 < nk) {
            a4 = *(const float4*)(Ap + (size_t)(t + 1) * 8);
            b4 = *(const float4*)(Bp + (size_t)(t + 1) * 8);
        }
#pragma unroll
        for (int kk = 0; kk < 8; kk++) {
            float a[8], b[8];
            *(float4*)(a)     = *(const float4*)&As[buf][kk][tm];
            *(float4*)(a + 4) = *(const float4*)&As[buf][kk][tm + 4];
            *(float4*)(b)     = *(const float4*)&Bs[buf][kk][tn];
            *(float4*)(b + 4) = *(const float4*)&Bs[buf][kk][tn + 4];
#pragma unroll
            for (int i = 0; i < 8; i++)
#pragma unroll
                for (int j = 0; j < 8; j++)
                    acc[i][j] += a[i] * b[j];
        }
        if (t + 1 < nk) {
            const int nb = buf ^ 1;
            As[nb][lk+0][lrow] = a4.x; As[nb][lk+1][lrow] = a4.y;
            As[nb][lk+2][lrow] = a4.z; As[nb][lk+3][lrow] = a4.w;
            Bs[nb][lk+0][lrow] = b4.x; Bs[nb][lk+1][lrow] = b4.y;
            Bs[nb][lk+2][lrow] = b4.z; Bs[nb][lk+3][lrow] = b4.w;
        }
        __syncthreads();
        buf ^= 1;
    }

#pragma unroll
    for (int i = 0; i < 8; i++) {
        float* Cp = C + (size_t)(bm + tm + i) * N + bn + tn;
        *(float4*)(Cp)     = make_float4(acc[i][0], acc[i][1], acc[i][2], acc[i][3]);
        *(float4*)(Cp + 4) = make_float4(acc[i][4], acc[i][5], acc[i][6], acc[i][7]);
    }
}

// ---------------------------------------------------------------------------
// LayerNorm (+bias, optional relu) over rows of length 1024. 256 thr/row.
// Safe in-place (in == out).
// ---------------------------------------------------------------------------
__global__ void __launch_bounds__(256) ln_kernel(
    const float* __restrict__ in, const float* __restrict__ bias,
    const float* __restrict__ gw, const float* __restrict__ bw,
    float* __restrict__ out, int do_relu)
{
    const size_t base = (size_t)blockIdx.x * DD;
    const int t = threadIdx.x;

    float4 v = *(const float4*)(in + base + t * 4);
    const float4 bb = *(const float4*)(bias + t * 4);
    v.x += bb.x; v.y += bb.y; v.z += bb.z; v.w += bb.w;

    float s1 = v.x + v.y + v.z + v.w;
    float s2 = v.x * v.x + v.y * v.y + v.z * v.z + v.w * v.w;
#pragma unroll
    for (int o = 16; o > 0; o >>= 1) {
        s1 += __shfl_xor_sync(0xffffffffu, s1, o);
        s2 += __shfl_xor_sync(0xffffffffu, s2, o);
    }
    __shared__ float sh1[8], sh2[8], stats[2];
    if ((t & 31) == 0) { sh1[t >> 5] = s1; sh2[t >> 5] = s2; }
    __syncthreads();
    if (t == 0) {
        float a = 0.f, b = 0.f;
#pragma unroll
        for (int i = 0; i < 8; i++) { a += sh1[i]; b += sh2[i]; }
        const float mean = a * (1.f / DD);
        const float var  = b * (1.f / DD) - mean * mean;
        stats[0] = mean;
        stats[1] = rsqrtf(var + 1e-5f);
    }
    __syncthreads();
    const float mean = stats[0], rstd = stats[1];

    const float4 g4 = *(const float4*)(gw + t * 4);
    const float4 b4 = *(const float4*)(bw + t * 4);
    float4 r;
    r.x = (v.x - mean) * rstd * g4.x + b4.x;
    r.y = (v.y - mean) * rstd * g4.y + b4.y;
    r.z = (v.z - mean) * rstd * g4.z + b4.z;
    r.w = (v.w - mean) * rstd * g4.w + b4.w;
    if (do_relu) {
        r.x = fmaxf(r.x, 0.f); r.y = fmaxf(r.y, 0.f);
        r.z = fmaxf(r.z, 0.f); r.w = fmaxf(r.w, 0.f);
    }
    *(float4*)(out + base + t * 4) = r;
}

// ---------------------------------------------------------------------------
// H[i,:] = 0.5 * ( relu(Za[i,:]+b1) + relu(Zt[i,:]+b1) ) ; rows of 2048
// ---------------------------------------------------------------------------
__global__ void __launch_bounds__(512) h_kernel(
    const float* __restrict__ Za, const float* __restrict__ Zt,
    const float* __restrict__ b1, float* __restrict__ Hout)
{
    const size_t base = (size_t)blockIdx.x * HD;
    const int j = threadIdx.x * 4;
    const float4 za = *(const float4*)(Za + base + j);
    const float4 zt = *(const float4*)(Zt + base + j);
    const float4 bb = *(const float4*)(b1 + j);
    float4 r;
    r.x = 0.5f * (fmaxf(za.x + bb.x, 0.f) + fmaxf(zt.x + bb.x, 0.f));
    r.y = 0.5f * (fmaxf(za.y + bb.y, 0.f) + fmaxf(zt.y + bb.y, 0.f));
    r.z = 0.5f * (fmaxf(za.z + bb.z, 0.f) + fmaxf(zt.z + bb.z, 0.f));
    r.w = 0.5f * (fmaxf(za.w + bb.w, 0.f) + fmaxf(zt.w + bb.w, 0.f));
    *(float4*)(Hout + base + j) = r;
}

// ---------------------------------------------------------------------------
// Transpose W2 [1024,2048] -> W2T [2048,1024]
// ---------------------------------------------------------------------------
__global__ void transpose_kernel(const float* __restrict__ in, float* __restrict__ out)
{
    __shared__ float tile[32][33];
    const int x  = blockIdx.x * 32 + threadIdx.x;   // col of in (0..2047)
    const int y0 = blockIdx.y * 32;                 // row of in
    for (int j = threadIdx.y; j < 32; j += 8)
        tile[j][threadIdx.x] = in[(size_t)(y0 + j) * HD + x];
    __syncthreads();
    const int ox  = blockIdx.y * 32 + threadIdx.x;  // col of out (0..1023)
    const int oy0 = blockIdx.x * 32;
    for (int j = threadIdx.y; j < 32; j += 8)
        out[(size_t)(oy0 + j) * DD + ox] = tile[threadIdx.x][j];
}

// bc[i] = sum_k Wf[i,k]*b2[k] + bf[i]
__global__ void bc_kernel(const float* __restrict__ Wf, const float* __restrict__ b2,
                          const float* __restrict__ bf, float* __restrict__ bc)
{
    const int i = blockIdx.x * 256 + threadIdx.x;
    float s = 0.f;
    for (int k = 0; k < DD; k++) s += Wf[(size_t)i * DD + k] * b2[k];
    bc[i] = s + bf[i];
}

// ---------------------------------------------------------------------------
// GAT1 attention fixup on nodes 0 (=Za row0) and 1 (=Zt row0). In-place.
// ---------------------------------------------------------------------------
__global__ void __launch_bounds__(1024) fixup1_kernel(
    float* Za, float* Zt, const float* __restrict__ as1, const float* __restrict__ ad1)
{
    const int t = threadIdx.x;                 // 1024
    const int wid = t >> 5, lane = t & 31;
    __shared__ float red[32][8];
    __shared__ float coef[8];

    float za[2], zt[2], p[8];
#pragma unroll
    for (int h = 0; h < 2; h++) {
        const int j = h * DD + t;
        const float a = as1[j], d = ad1[j];
        za[h] = Za[j]; zt[h] = Zt[j];
        p[h*4+0] = za[h] * a;   // s[node0][h]
        p[h*4+1] = za[h] * d;   // d[node0][h]
        p[h*4+2] = zt[h] * a;   // s[node1][h]
        p[h*4+3] = zt[h] * d;   // d[node1][h]
    }
#pragma unroll
    for (int i = 0; i < 8; i++)
#pragma unroll
        for (int o = 16; o > 0; o >>= 1)
            p[i] += __shfl_xor_sync(0xffffffffu, p[i], o);
    if (lane == 0)
#pragma unroll
        for (int i = 0; i < 8; i++) red[wid][i] = p[i];
    __syncthreads();
    if (t == 0) {
        float S[8];
#pragma unroll
        for (int i = 0; i < 8; i++) {
            float s = 0.f;
            for (int wv = 0; wv < 32; wv++) s += red[wv][i];
            S[i] = s;
        }
        for (int h = 0; h < 2; h++) {
            const float s0 = S[h*4+0], d0 = S[h*4+1], s1 = S[h*4+2], d1 = S[h*4+3];
            const float e00 = lrelu_f(s0 + d0), e10 = lrelu_f(s1 + d0);
            const float m0 = fmaxf(e00, e10);
            const float q0 = expf(e00 - m0), q1 = expf(e10 - m0);
            coef[h*4+0] = q0 / (q0 + q1); coef[h*4+1] = q1 / (q0 + q1);
            const float e11 = lrelu_f(s1 + d1), e01 = lrelu_f(s0 + d1);
            const float m1 = fmaxf(e11, e01);
            const float r0 = expf(e11 - m1), r1 = expf(e01 - m1);
            coef[h*4+2] = r0 / (r0 + r1); coef[h*4+3] = r1 / (r0 + r1);
        }
    }
    __syncthreads();
#pragma unroll
    for (int h = 0; h < 2; h++) {
        const int j = h * DD + t;
        Za[j] = coef[h*4+0] * za[h] + coef[h*4+1] * zt[h];   // node0 mixed
        Zt[j] = coef[h*4+2] * zt[h] + coef[h*4+3] * za[h];   // node1 mixed
    }
}

// xp2[n] = relu(z_n + b1) @ W2^T  for nodes n=0,1 (z rows already mixed)
__global__ void fixup2a_kernel(
    const float* __restrict__ Za, const float* __restrict__ Zt,
    const float* __restrict__ b1, const float* __restrict__ W2,
    float* __restrict__ xp2)
{
    const int i = blockIdx.x * 128 + threadIdx.x;   // 8 blocks x 128 = 1024
    float a0 = 0.f, a1 = 0.f;
    for (int j = 0; j < HD; j++) {
        const float g0 = fmaxf(Za[j] + b1[j], 0.f);
        const float g1 = fmaxf(Zt[j] + b1[j], 0.f);
        const float wv = W2[(size_t)i * HD + j];
        a0 += g0 * wv; a1 += g1 * wv;
    }
    xp2[i] = a0; xp2[DD + i] = a1;
}

// GAT2 attention coefficients for pair 0; rewrite H row 0 = 0.5*(c0*g0 + c1*g1)
__global__ void __launch_bounds__(1024) fixup2b_kernel(
    const float* __restrict__ xp2, const float* __restrict__ as2,
    const float* __restrict__ ad2, const float* __restrict__ Za,
    const float* __restrict__ Zt, const float* __restrict__ b1,
    float* __restrict__ Hrow)
{
    const int t = threadIdx.x;            // 1024
    const int wid = t >> 5, lane = t & 31;
    __shared__ float red[32][4];
    __shared__ float cf[2];

    const float x0 = xp2[t], x1 = xp2[DD + t];
    const float a = as2[t], d = ad2[t];
    float p[4] = { x0 * a, x0 * d, x1 * a, x1 * d };
#pragma unroll
    for (int i = 0; i < 4; i++)
#pragma unroll
        for (int o = 16; o > 0; o >>= 1)
            p[i] += __shfl_xor_sync(0xffffffffu, p[i], o);
    if (lane == 0)
#pragma unroll
        for (int i = 0; i < 4; i++) red[wid][i] = p[i];
    __syncthreads();
    if (t == 0) {
        float S[4];
#pragma unroll
        for (int i = 0; i < 4; i++) {
            float s = 0.f;
            for (int wv = 0; wv < 32; wv++) s += red[wv][i];
            S[i] = s;
        }
        const float s0 = S[0], d0 = S[1], s1 = S[2], d1 = S[3];
        const float e00 = lrelu_f(s0 + d0), e10 = lrelu_f(s1 + d0);
        const float m0 = fmaxf(e00, e10);
        const float q0 = expf(e00 - m0), q1 = expf(e10 - m0);
        const float w0s = q0 / (q0 + q1), w0o = q1 / (q0 + q1);
        const float e11 = lrelu_f(s1 + d1), e01 = lrelu_f(s0 + d1);
        const float m1 = fmaxf(e11, e01);
        const float r0 = expf(e11 - m1), r1 = expf(e01 - m1);
        const float w1s = r0 / (r0 + r1), w1o = r1 / (r0 + r1);
        cf[0] = w0s + w1o;   // coefficient on node0's xp2
        cf[1] = w0o + w1s;   // coefficient on node1's xp2
    }
    __syncthreads();
#pragma unroll
    for (int h = 0; h < 2; h++) {
        const int j = h * DD + t;
        const float g0 = fmaxf(Za[j] + b1[j], 0.f);
        const float g1 = fmaxf(Zt[j] + b1[j], 0.f);
        Hrow[j] = 0.5f * (cf[0] * g0 + cf[1] * g1);
    }
}

// ---------------------------------------------------------------------------
// Launch
// ---------------------------------------------------------------------------
extern "C" void kernel_launch(void* const* d_in, const int* in_sizes, int n_in,
                              void* d_out, int out_size)
{
    const float* audio = (const float*)d_in[0];
    const float* text  = (const float*)d_in[1];
    const float* Wa    = (const float*)d_in[2];
    const float* ba    = (const float*)d_in[3];
    const float* lna_g = (const float*)d_in[4];
    const float* lna_b = (const float*)d_in[5];
    const float* Wt    = (const float*)d_in[6];
    const float* bt    = (const float*)d_in[7];
    const float* lnt_g = (const float*)d_in[8];
    const float* lnt_b = (const float*)d_in[9];
    const float* W1    = (const float*)d_in[10];
    const float* as1   = (const float*)d_in[11];
    const float* ad1   = (const float*)d_in[12];
    const float* b1    = (const float*)d_in[13];
    const float* W2    = (const float*)d_in[14];
    const float* as2   = (const float*)d_in[15];
    const float* ad2   = (const float*)d_in[16];
    const float* b2    = (const float*)d_in[17];
    const float* Wf    = (const float*)d_in[18];
    const float* bf    = (const float*)d_in[19];
    const float* lnf_g = (const float*)d_in[20];
    const float* lnf_b = (const float*)d_in[21];
    float* out = (float*)d_out;

    float *Xa, *Xt, *Za, *Zt, *Hb, *W2T, *Wc, *bc, *xp2;
    cudaGetSymbolAddress((void**)&Xa,  g_Xa);
    cudaGetSymbolAddress((void**)&Xt,  g_Xt);
    cudaGetSymbolAddress((void**)&Za,  g_Za);
    cudaGetSymbolAddress((void**)&Zt,  g_Zt);
    cudaGetSymbolAddress((void**)&Hb,  g_H);
    cudaGetSymbolAddress((void**)&W2T, g_W2T);
    cudaGetSymbolAddress((void**)&Wc,  g_Wc);
    cudaGetSymbolAddress((void**)&bc,  g_bc);
    cudaGetSymbolAddress((void**)&xp2, g_xp2);

    // Fold fc into gat2:  Wc = Wf @ W2  (via W2T so sgemm_nt applies), bc = Wf@b2 + bf
    transpose_kernel<<<dim3(HD / 32, DD / 32), dim3(32, 8)>>>(W2, W2T);
    sgemm_nt<<<dim3(HD / 128, DD / 128), 256>>>(Wf, W2T, Wc, DD, HD, DD);
    bc_kernel<<<DD / 256, 256>>>(Wf, b2, bf, bc);

    // proj + LN + relu (GEMM temp reuses Za/Zt buffers)
    sgemm_nt<<<dim3(DD / 128, NB / 128), 256>>>(audio, Wa, Za, NB, DD, DD);
    ln_kernel<<<NB, 256>>>(Za, ba, lna_g, lna_b, Xa, 1);
    sgemm_nt<<<dim3(DD / 128, NB / 128), 256>>>(text, Wt, Zt, NB, DD, DD);
    ln_kernel<<<NB, 256>>>(Zt, bt, lnt_g, lnt_b, Xt, 1);

    // GAT1 linear part
    sgemm_nt<<<dim3(HD / 128, NB / 128), 256>>>(Xa, W1, Za, NB, HD, DD);
    sgemm_nt<<<dim3(HD / 128, NB / 128), 256>>>(Xt, W1, Zt, NB, HD, DD);

    // pair-0 attention (GAT1), then relu+average, then pair-0 (GAT2) fix on H row 0
    fixup1_kernel<<<1, 1024>>>(Za, Zt, as1, ad1);
    h_kernel<<<NB, 512>>>(Za, Zt, b1, Hb);
    fixup2a_kernel<<<8, 128>>>(Za, Zt, b1, W2, xp2);
    fixup2b_kernel<<<1, 1024>>>(xp2, as2, ad2, Za, Zt, b1, Hb);

    // fused GAT2+fc GEMM, then final LN in-place on d_out
    sgemm_nt<<<dim3(DD / 128, NB / 128), 256>>>(Hb, Wc, out, NB, DD, HD);
    ln_kernel<<<NB, 256>>>(out, bc, lnf_g, lnf_b, out, 0);
}

// round 3
// speedup vs baseline: 2.5233x; 2.5233x over previous
#include <cuda_runtime.h>
#include <cuda_bf16.h>
#include <cstdint>
#include <cstddef>

#define NB 16384
#define DD 1024
#define HD 2048
#define K3A (3*DD)
#define K3H (3*HD)

// ---------------------------------------------------------------------------
// Scratch (device globals)
// ---------------------------------------------------------------------------
__device__ float g_Za[(size_t)NB * HD];
__device__ float g_Zt[(size_t)NB * HD];
__device__ float g_W2T[(size_t)HD * DD];
__device__ float g_Wc [(size_t)DD * HD];
__device__ float g_bc [DD];
__device__ float g_xp2[2 * DD];
__device__ __nv_bfloat16 g_Aa3[(size_t)NB * K3A];
__device__ __nv_bfloat16 g_At3[(size_t)NB * K3A];
__device__ __nv_bfloat16 g_H3 [(size_t)NB * K3H];
__device__ __nv_bfloat16 g_Wa3[(size_t)DD * K3A];
__device__ __nv_bfloat16 g_Wt3[(size_t)DD * K3A];
__device__ __nv_bfloat16 g_W13[(size_t)HD * K3A];
__device__ __nv_bfloat16 g_Wc3[(size_t)DD * K3H];

__device__ __forceinline__ float lrelu_f(float v) { return v > 0.f ? v : 0.2f * v; }

// ---------------------------------------------------------------------------
// PTX helpers (sm_80-era only: cp.async, ldmatrix, mma.sync)
// ---------------------------------------------------------------------------
__device__ __forceinline__ uint32_t smem_u32(const void* p) {
    uint32_t a;
    asm("{ .reg .u64 t; cvta.to.shared.u64 t, %1; cvt.u32.u64 %0, t; }" : "=r"(a) : "l"(p));
    return a;
}
__device__ __forceinline__ void cp_async16(uint32_t s, const void* g) {
    asm volatile("cp.async.cg.shared.global [%0], [%1], 16;\n" :: "r"(s), "l"(g));
}
__device__ __forceinline__ uint32_t sw(uint32_t off) { return off ^ ((off >> 3) & 0x70); }

__device__ __forceinline__ void ldsm_x4(uint32_t (&r)[4], uint32_t addr) {
    asm volatile("ldmatrix.sync.aligned.m8n8.x4.shared.b16 {%0,%1,%2,%3}, [%4];"
        : "=r"(r[0]), "=r"(r[1]), "=r"(r[2]), "=r"(r[3]) : "r"(addr));
}
__device__ __forceinline__ void mma_bf16(float (&c)[4], const uint32_t (&a)[4],
                                         uint32_t b0, uint32_t b1) {
    asm volatile("mma.sync.aligned.m16n8k16.row.col.f32.bf16.bf16.f32 "
        "{%0,%1,%2,%3}, {%4,%5,%6,%7}, {%8,%9}, {%0,%1,%2,%3};"
        : "+f"(c[0]), "+f"(c[1]), "+f"(c[2]), "+f"(c[3])
        : "r"(a[0]), "r"(a[1]), "r"(a[2]), "r"(a[3]), "r"(b0), "r"(b1));
}

// ---------------------------------------------------------------------------
// bf16 GEMM via mma.sync: C[M,N] = A3[M,K3] * B3[N,K3]^T (fp32 accum)
// CTA tile 128x128, BK=64, 3-stage cp.async pipeline, 256 threads (8 warps
// as 4(m) x 2(n), warp tile 32x64).
// ---------------------------------------------------------------------------
#define BM 128
#define BN 128
#define BK 64
#define NST 3
#define HTILE 16384                       // 128 rows * 128 bytes
#define STAGE_BYTES (2 * HTILE)
#define MM_SMEM (NST * STAGE_BYTES)       // 98304

__global__ void __launch_bounds__(256, 2) mma_gemm(
    const __nv_bfloat16* __restrict__ A, const __nv_bfloat16* __restrict__ B,
    float* __restrict__ C, int M, int N, int K3)
{
    extern __shared__ char smem[];
    const uint32_t sb = smem_u32(smem);
    const int tid = threadIdx.x;
    const int bm = blockIdx.y * BM;
    const int bn = blockIdx.x * BN;
    const int nk = K3 / BK;

    const int wid = tid >> 5, lane = tid & 31;
    const int wm = (wid & 3) * 32;
    const int wn = (wid >> 2) * 64;

    float acc[2][8][4];
#pragma unroll
    for (int i = 0; i < 2; i++)
#pragma unroll
        for (int j = 0; j < 8; j++)
#pragma unroll
            for (int k = 0; k < 4; k++) acc[i][j][k] = 0.f;

    auto load_stage = [&](int chunk, int slot) {
        const size_t kb = (size_t)chunk * BK;
        const uint32_t sA = sb + slot * STAGE_BYTES;
        const uint32_t sB = sA + HTILE;
#pragma unroll
        for (int i = 0; i < 4; i++) {
            const int c = tid + i * 256;
            const int row = c >> 3, kc = c & 7;
            cp_async16(sA + sw(row * 128 + kc * 16),
                       A + (size_t)(bm + row) * K3 + kb + kc * 8);
        }
#pragma unroll
        for (int i = 0; i < 4; i++) {
            const int c = tid + i * 256;
            const int row = c >> 3, kc = c & 7;
            cp_async16(sB + sw(row * 128 + kc * 16),
                       B + (size_t)(bn + row) * K3 + kb + kc * 8);
        }
        asm volatile("cp.async.commit_group;\n" ::: "memory");
    };

    load_stage(0, 0);
    load_stage(1, 1);

    for (int t = 0; t < nk; t++) {
        if (t + 2 < nk) asm volatile("cp.async.wait_group 1;\n" ::: "memory");
        else            asm volatile("cp.async.wait_group 0;\n" ::: "memory");
        __syncthreads();

        const uint32_t aS = sb + (t % NST) * STAGE_BYTES;
        const uint32_t bS = aS + HTILE;
#pragma unroll
        for (int ks = 0; ks < 4; ks++) {
            uint32_t af[2][4];
#pragma unroll
            for (int mf = 0; mf < 2; mf++) {
                const uint32_t row = wm + mf * 16 + (lane & 15);
                const uint32_t off = row * 128 + ks * 32 + ((lane >> 4) << 4);
                ldsm_x4(af[mf], aS + sw(off));
            }
            uint32_t bfr[8][2];
#pragma unroll
            for (int np = 0; np < 4; np++) {
                const uint32_t row = wn + np * 16 + ((lane >> 4) << 3) + (lane & 7);
                const uint32_t off = row * 128 + ks * 32 + (((lane >> 3) & 1) << 4);
                uint32_t r[4];
                ldsm_x4(r, bS + sw(off));
                bfr[2*np][0] = r[0]; bfr[2*np][1] = r[1];
                bfr[2*np+1][0] = r[2]; bfr[2*np+1][1] = r[3];
            }
#pragma unroll
            for (int mf = 0; mf < 2; mf++)
#pragma unroll
                for (int nf = 0; nf < 8; nf++)
                    mma_bf16(acc[mf][nf], af[mf], bfr[nf][0], bfr[nf][1]);
        }

        if (t + 2 < nk) load_stage(t + 2, (t + 2) % NST);
    }

    // epilogue: c0,c1 -> row gid, cols qid*2+{0,1}; c2,c3 -> row gid+8
    const int gid = lane >> 2, qid = lane & 3;
#pragma unroll
    for (int mf = 0; mf < 2; mf++) {
#pragma unroll
        for (int half = 0; half < 2; half++) {
            const int row = bm + wm + mf * 16 + gid + half * 8;
            float* Cr = C + (size_t)row * N + bn + wn + qid * 2;
#pragma unroll
            for (int nf = 0; nf < 8; nf++) {
                float2 v = make_float2(acc[mf][nf][half * 2], acc[mf][nf][half * 2 + 1]);
                *(float2*)(Cr + nf * 8) = v;
            }
        }
    }
}

// ---------------------------------------------------------------------------
// fp32 -> bf16 hi/lo split helpers + conversion kernels
// ---------------------------------------------------------------------------
__device__ __forceinline__ void split2(float a, float b, __nv_bfloat162& h, __nv_bfloat162& l) {
    __nv_bfloat16 ha = __float2bfloat16(a), hb = __float2bfloat16(b);
    h.x = ha; h.y = hb;
    l.x = __float2bfloat16(a - __bfloat162float(ha));
    l.y = __float2bfloat16(b - __bfloat162float(hb));
}

// activation layout: [hi | hi | lo]
__global__ void convA3_kernel(const float* __restrict__ in, __nv_bfloat16* __restrict__ out, int K)
{
    const size_t idx = (size_t)blockIdx.x * blockDim.x + threadIdx.x;
    const int kq = (int)(idx % (K / 4)) * 4;
    const size_t m = idx / (K / 4);
    const float4 v = *(const float4*)(in + m * K + kq);
    __nv_bfloat162 h0, l0, h1, l1;
    split2(v.x, v.y, h0, l0); split2(v.z, v.w, h1, l1);
    __nv_bfloat16* base = out + m * (size_t)(3 * K) + kq;
    *(__nv_bfloat162*)(base)         = h0; *(__nv_bfloat162*)(base + 2)         = h1;
    *(__nv_bfloat162*)(base + K)     = h0; *(__nv_bfloat162*)(base + K + 2)     = h1;
    *(__nv_bfloat162*)(base + 2 * K) = l0; *(__nv_bfloat162*)(base + 2 * K + 2) = l1;
}

// weight layout: [hi | lo | hi]
__global__ void convB3_kernel(const float* __restrict__ in, __nv_bfloat16* __restrict__ out, int K)
{
    const size_t idx = (size_t)blockIdx.x * blockDim.x + threadIdx.x;
    const int kq = (int)(idx % (K / 4)) * 4;
    const size_t m = idx / (K / 4);
    const float4 v = *(const float4*)(in + m * K + kq);
    __nv_bfloat162 h0, l0, h1, l1;
    split2(v.x, v.y, h0, l0); split2(v.z, v.w, h1, l1);
    __nv_bfloat16* base = out + m * (size_t)(3 * K) + kq;
    *(__nv_bfloat162*)(base)         = h0; *(__nv_bfloat162*)(base + 2)         = h1;
    *(__nv_bfloat162*)(base + K)     = l0; *(__nv_bfloat162*)(base + K + 2)     = l1;
    *(__nv_bfloat162*)(base + 2 * K) = h0; *(__nv_bfloat162*)(base + 2 * K + 2) = h1;
}

// ---------------------------------------------------------------------------
// LayerNorm fp32 (final) and LN->relu->tripled-bf16 (mid)
// ---------------------------------------------------------------------------
__global__ void __launch_bounds__(256) ln_kernel(
    const float* __restrict__ in, const float* __restrict__ bias,
    const float* __restrict__ gw, const float* __restrict__ bw,
    float* __restrict__ out)
{
    const size_t base = (size_t)blockIdx.x * DD;
    const int t = threadIdx.x;
    float4 v = *(const float4*)(in + base + t * 4);
    const float4 bb = *(const float4*)(bias + t * 4);
    v.x += bb.x; v.y += bb.y; v.z += bb.z; v.w += bb.w;
    float s1 = v.x + v.y + v.z + v.w;
    float s2 = v.x * v.x + v.y * v.y + v.z * v.z + v.w * v.w;
#pragma unroll
    for (int o = 16; o > 0; o >>= 1) {
        s1 += __shfl_xor_sync(0xffffffffu, s1, o);
        s2 += __shfl_xor_sync(0xffffffffu, s2, o);
    }
    __shared__ float sh1[8], sh2[8], stats[2];
    if ((t & 31) == 0) { sh1[t >> 5] = s1; sh2[t >> 5] = s2; }
    __syncthreads();
    if (t == 0) {
        float a = 0.f, b = 0.f;
#pragma unroll
        for (int i = 0; i < 8; i++) { a += sh1[i]; b += sh2[i]; }
        const float mean = a * (1.f / DD);
        stats[0] = mean;
        stats[1] = rsqrtf(b * (1.f / DD) - mean * mean + 1e-5f);
    }
    __syncthreads();
    const float mean = stats[0], rstd = stats[1];
    const float4 g4 = *(const float4*)(gw + t * 4);
    const float4 b4 = *(const float4*)(bw + t * 4);
    float4 r;
    r.x = (v.x - mean) * rstd * g4.x + b4.x;
    r.y = (v.y - mean) * rstd * g4.y + b4.y;
    r.z = (v.z - mean) * rstd * g4.z + b4.z;
    r.w = (v.w - mean) * rstd * g4.w + b4.w;
    *(float4*)(out + base + t * 4) = r;
}

__global__ void __launch_bounds__(256) ln3_kernel(
    const float* __restrict__ in, const float* __restrict__ bias,
    const float* __restrict__ gw, const float* __restrict__ bw,
    __nv_bfloat16* __restrict__ out)  // [hi|hi|lo], row stride 3*DD, with relu
{
    const size_t base = (size_t)blockIdx.x * DD;
    const int t = threadIdx.x;
    float4 v = *(const float4*)(in + base + t * 4);
    const float4 bb = *(const float4*)(bias + t * 4);
    v.x += bb.x; v.y += bb.y; v.z += bb.z; v.w += bb.w;
    float s1 = v.x + v.y + v.z + v.w;
    float s2 = v.x * v.x + v.y * v.y + v.z * v.z + v.w * v.w;
#pragma unroll
    for (int o = 16; o > 0; o >>= 1) {
        s1 += __shfl_xor_sync(0xffffffffu, s1, o);
        s2 += __shfl_xor_sync(0xffffffffu, s2, o);
    }
    __shared__ float sh1[8], sh2[8], stats[2];
    if ((t & 31) == 0) { sh1[t >> 5] = s1; sh2[t >> 5] = s2; }
    __syncthreads();
    if (t == 0) {
        float a = 0.f, b = 0.f;
#pragma unroll
        for (int i = 0; i < 8; i++) { a += sh1[i]; b += sh2[i]; }
        const float mean = a * (1.f / DD);
        stats[0] = mean;
        stats[1] = rsqrtf(b * (1.f / DD) - mean * mean + 1e-5f);
    }
    __syncthreads();
    const float mean = stats[0], rstd = stats[1];
    const float4 g4 = *(const float4*)(gw + t * 4);
    const float4 b4 = *(const float4*)(bw + t * 4);
    float4 r;
    r.x = fmaxf((v.x - mean) * rstd * g4.x + b4.x, 0.f);
    r.y = fmaxf((v.y - mean) * rstd * g4.y + b4.y, 0.f);
    r.z = fmaxf((v.z - mean) * rstd * g4.z + b4.z, 0.f);
    r.w = fmaxf((v.w - mean) * rstd * g4.w + b4.w, 0.f);
    __nv_bfloat162 h0, l0, h1, l1;
    split2(r.x, r.y, h0, l0); split2(r.z, r.w, h1, l1);
    __nv_bfloat16* ob = out + (size_t)blockIdx.x * K3A + t * 4;
    *(__nv_bfloat162*)(ob)          = h0; *(__nv_bfloat162*)(ob + 2)          = h1;
    *(__nv_bfloat162*)(ob + DD)     = h0; *(__nv_bfloat162*)(ob + DD + 2)     = h1;
    *(__nv_bfloat162*)(ob + 2 * DD) = l0; *(__nv_bfloat162*)(ob + 2 * DD + 2) = l1;
}

// H row = 0.5*(relu(Za+b1)+relu(Zt+b1)) -> tripled bf16 [hi|hi|lo], stride 3*HD
__global__ void __launch_bounds__(512) h3_kernel(
    const float* __restrict__ Za, const float* __restrict__ Zt,
    const float* __restrict__ b1, __nv_bfloat16* __restrict__ H3)
{
    const size_t base = (size_t)blockIdx.x * HD;
    const int j = threadIdx.x * 4;
    const float4 za = *(const float4*)(Za + base + j);
    const float4 zt = *(const float4*)(Zt + base + j);
    const float4 bb = *(const float4*)(b1 + j);
    float4 r;
    r.x = 0.5f * (fmaxf(za.x + bb.x, 0.f) + fmaxf(zt.x + bb.x, 0.f));
    r.y = 0.5f * (fmaxf(za.y + bb.y, 0.f) + fmaxf(zt.y + bb.y, 0.f));
    r.z = 0.5f * (fmaxf(za.z + bb.z, 0.f) + fmaxf(zt.z + bb.z, 0.f));
    r.w = 0.5f * (fmaxf(za.w + bb.w, 0.f) + fmaxf(zt.w + bb.w, 0.f));
    __nv_bfloat162 h0, l0, h1, l1;
    split2(r.x, r.y, h0, l0); split2(r.z, r.w, h1, l1);
    __nv_bfloat16* ob = H3 + (size_t)blockIdx.x * K3H + j;
    *(__nv_bfloat162*)(ob)          = h0; *(__nv_bfloat162*)(ob + 2)          = h1;
    *(__nv_bfloat162*)(ob + HD)     = h0; *(__nv_bfloat162*)(ob + HD + 2)     = h1;
    *(__nv_bfloat162*)(ob + 2 * HD) = l0; *(__nv_bfloat162*)(ob + 2 * HD + 2) = l1;
}

// ---------------------------------------------------------------------------
// fp32 SGEMM (for the small Wc = Wf @ W2 fold) + transpose + bc
// ---------------------------------------------------------------------------
__global__ void __launch_bounds__(256) sgemm_nt(
    const float* __restrict__ A, const float* __restrict__ B,
    float* __restrict__ C, int M, int N, int K)
{
    __shared__ float As[2][8][128];
    __shared__ float Bs[2][8][128];
    const int tid = threadIdx.x;
    const int bm = blockIdx.y * 128, bn = blockIdx.x * 128;
    const int lrow = tid >> 1, lk = (tid & 1) << 2;
    const float* Ap = A + (size_t)(bm + lrow) * K + lk;
    const float* Bp = B + (size_t)(bn + lrow) * K + lk;
    const int w = tid >> 5, l = tid & 31;
    const int tm = (w & 3) * 32 + (l >> 3) * 8;
    const int tn = (w >> 2) * 64 + (l & 7) * 8;
    float acc[8][8];
#pragma unroll
    for (int i = 0; i < 8; i++)
#pragma unroll
        for (int j = 0; j < 8; j++) acc[i][j] = 0.f;
    float4 a4 = *(const float4*)Ap;
    float4 b4 = *(const float4*)Bp;
    As[0][lk+0][lrow] = a4.x; As[0][lk+1][lrow] = a4.y;
    As[0][lk+2][lrow] = a4.z; As[0][lk+3][lrow] = a4.w;
    Bs[0][lk+0][lrow] = b4.x; Bs[0][lk+1][lrow] = b4.y;
    Bs[0][lk+2][lrow] = b4.z; Bs[0][lk+3][lrow] = b4.w;
    __syncthreads();
    const int nk = K >> 3;
    int buf = 0;
    for (int t = 0; t < nk; t++) {
        if (t + 1 < nk) {
            a4 = *(const float4*)(Ap + (size_t)(t + 1) * 8);
            b4 = *(const float4*)(Bp + (size_t)(t + 1) * 8);
        }
#pragma unroll
        for (int kk = 0; kk < 8; kk++) {
            float a[8], b[8];
            *(float4*)(a)     = *(const float4*)&As[buf][kk][tm];
            *(float4*)(a + 4) = *(const float4*)&As[buf][kk][tm + 4];
            *(float4*)(b)     = *(const float4*)&Bs[buf][kk][tn];
            *(float4*)(b + 4) = *(const float4*)&Bs[buf][kk][tn + 4];
#pragma unroll
            for (int i = 0; i < 8; i++)
#pragma unroll
                for (int j = 0; j < 8; j++) acc[i][j] += a[i] * b[j];
        }
        if (t + 1 < nk) {
            const int nb = buf ^ 1;
            As[nb][lk+0][lrow] = a4.x; As[nb][lk+1][lrow] = a4.y;
            As[nb][lk+2][lrow] = a4.z; As[nb][lk+3][lrow] = a4.w;
            Bs[nb][lk+0][lrow] = b4.x; Bs[nb][lk+1][lrow] = b4.y;
            Bs[nb][lk+2][lrow] = b4.z; Bs[nb][lk+3][lrow] = b4.w;
        }
        __syncthreads();
        buf ^= 1;
    }
#pragma unroll
    for (int i = 0; i < 8; i++) {
        float* Cp = C + (size_t)(bm + tm + i) * N + bn + tn;
        *(float4*)(Cp)     = make_float4(acc[i][0], acc[i][1], acc[i][2], acc[i][3]);
        *(float4*)(Cp + 4) = make_float4(acc[i][4], acc[i][5], acc[i][6], acc[i][7]);
    }
}

__global__ void transpose_kernel(const float* __restrict__ in, float* __restrict__ out)
{
    __shared__ float tile[32][33];
    const int x = blockIdx.x * 32 + threadIdx.x;
    const int y0 = blockIdx.y * 32;
    for (int j = threadIdx.y; j < 32; j += 8)
        tile[j][threadIdx.x] = in[(size_t)(y0 + j) * HD + x];
    __syncthreads();
    const int ox = blockIdx.y * 32 + threadIdx.x;
    const int oy0 = blockIdx.x * 32;
    for (int j = threadIdx.y; j < 32; j += 8)
        out[(size_t)(oy0 + j) * DD + ox] = tile[threadIdx.x][j];
}

__global__ void bc_kernel(const float* __restrict__ Wf, const float* __restrict__ b2,
                          const float* __restrict__ bf, float* __restrict__ bc)
{
    const int i = blockIdx.x * 256 + threadIdx.x;
    float s = 0.f;
    for (int k = 0; k < DD; k++) s += Wf[(size_t)i * DD + k] * b2[k];
    bc[i] = s + bf[i];
}

// ---------------------------------------------------------------------------
// Pair-0 fixups (exact GAT attention for nodes 0<->1)
// ---------------------------------------------------------------------------
__global__ void __launch_bounds__(1024) fixup1_kernel(
    float* Za, float* Zt, const float* __restrict__ as1, const float* __restrict__ ad1)
{
    const int t = threadIdx.x;
    const int wid = t >> 5, lane = t & 31;
    __shared__ float red[32][8];
    __shared__ float coef[8];
    float za[2], zt[2], p[8];
#pragma unroll
    for (int h = 0; h < 2; h++) {
        const int j = h * DD + t;
        const float a = as1[j], d = ad1[j];
        za[h] = Za[j]; zt[h] = Zt[j];
        p[h*4+0] = za[h] * a; p[h*4+1] = za[h] * d;
        p[h*4+2] = zt[h] * a; p[h*4+3] = zt[h] * d;
    }
#pragma unroll
    for (int i = 0; i < 8; i++)
#pragma unroll
        for (int o = 16; o > 0; o >>= 1) p[i] += __shfl_xor_sync(0xffffffffu, p[i], o);
    if (lane == 0)
#pragma unroll
        for (int i = 0; i < 8; i++) red[wid][i] = p[i];
    __syncthreads();
    if (t == 0) {
        float S[8];
#pragma unroll
        for (int i = 0; i < 8; i++) {
            float s = 0.f;
            for (int wv = 0; wv < 32; wv++) s += red[wv][i];
            S[i] = s;
        }
        for (int h = 0; h < 2; h++) {
            const float s0 = S[h*4+0], d0 = S[h*4+1], s1 = S[h*4+2], d1 = S[h*4+3];
            const float e00 = lrelu_f(s0 + d0), e10 = lrelu_f(s1 + d0);
            const float m0 = fmaxf(e00, e10);
            const float q0 = expf(e00 - m0), q1 = expf(e10 - m0);
            coef[h*4+0] = q0 / (q0 + q1); coef[h*4+1] = q1 / (q0 + q1);
            const float e11 = lrelu_f(s1 + d1), e01 = lrelu_f(s0 + d1);
            const float m1 = fmaxf(e11, e01);
            const float r0 = expf(e11 - m1), r1 = expf(e01 - m1);
            coef[h*4+2] = r0 / (r0 + r1); coef[h*4+3] = r1 / (r0 + r1);
        }
    }
    __syncthreads();
#pragma unroll
    for (int h = 0; h < 2; h++) {
        const int j = h * DD + t;
        Za[j] = coef[h*4+0] * za[h] + coef[h*4+1] * zt[h];
        Zt[j] = coef[h*4+2] * zt[h] + coef[h*4+3] * za[h];
    }
}

__global__ void fixup2a_kernel(
    const float* __restrict__ Za, const float* __restrict__ Zt,
    const float* __restrict__ b1, const float* __restrict__ W2,
    float* __restrict__ xp2)
{
    const int i = blockIdx.x * 128 + threadIdx.x;
    float a0 = 0.f, a1 = 0.f;
    for (int j = 0; j < HD; j++) {
        const float g0 = fmaxf(Za[j] + b1[j], 0.f);
        const float g1 = fmaxf(Zt[j] + b1[j], 0.f);
        const float wv = W2[(size_t)i * HD + j];
        a0 += g0 * wv; a1 += g1 * wv;
    }
    xp2[i] = a0; xp2[DD + i] = a1;
}

__global__ void __launch_bounds__(1024) fixup2b_kernel(
    const float* __restrict__ xp2, const float* __restrict__ as2,
    const float* __restrict__ ad2, const float* __restrict__ Za,
    const float* __restrict__ Zt, const float* __restrict__ b1,
    __nv_bfloat16* __restrict__ H3)   // rewrites row 0 (tripled layout)
{
    const int t = threadIdx.x;
    const int wid = t >> 5, lane = t & 31;
    __shared__ float red[32][4];
    __shared__ float cf[2];
    const float x0 = xp2[t], x1 = xp2[DD + t];
    const float a = as2[t], d = ad2[t];
    float p[4] = { x0 * a, x0 * d, x1 * a, x1 * d };
#pragma unroll
    for (int i = 0; i < 4; i++)
#pragma unroll
        for (int o = 16; o > 0; o >>= 1) p[i] += __shfl_xor_sync(0xffffffffu, p[i], o);
    if (lane == 0)
#pragma unroll
        for (int i = 0; i < 4; i++) red[wid][i] = p[i];
    __syncthreads();
    if (t == 0) {
        float S[4];
#pragma unroll
        for (int i = 0; i < 4; i++) {
            float s = 0.f;
            for (int wv = 0; wv < 32; wv++) s += red[wv][i];
            S[i] = s;
        }
        const float s0 = S[0], d0 = S[1], s1 = S[2], d1 = S[3];
        const float e00 = lrelu_f(s0 + d0), e10 = lrelu_f(s1 + d0);
        const float m0 = fmaxf(e00, e10);
        const float q0 = expf(e00 - m0), q1 = expf(e10 - m0);
        const float w0s = q0 / (q0 + q1), w0o = q1 / (q0 + q1);
        const float e11 = lrelu_f(s1 + d1), e01 = lrelu_f(s0 + d1);
        const float m1 = fmaxf(e11, e01);
        const float r0 = expf(e11 - m1), r1 = expf(e01 - m1);
        const float w1s = r0 / (r0 + r1), w1o = r1 / (r0 + r1);
        cf[0] = w0s + w1o;
        cf[1] = w0o + w1s;
    }
    __syncthreads();
#pragma unroll
    for (int h = 0; h < 2; h++) {
        const int j = h * DD + t;
        const float g0 = fmaxf(Za[j] + b1[j], 0.f);
        const float g1 = fmaxf(Zt[j] + b1[j], 0.f);
        const float hv = 0.5f * (cf[0] * g0 + cf[1] * g1);
        const __nv_bfloat16 hh = __float2bfloat16(hv);
        const __nv_bfloat16 ll = __float2bfloat16(hv - __bfloat162float(hh));
        H3[j] = hh; H3[HD + j] = hh; H3[2 * HD + j] = ll;
    }
}

// ---------------------------------------------------------------------------
// Launch
// ---------------------------------------------------------------------------
extern "C" void kernel_launch(void* const* d_in, const int* in_sizes, int n_in,
                              void* d_out, int out_size)
{
    const float* audio = (const float*)d_in[0];
    const float* text  = (const float*)d_in[1];
    const float* Wa    = (const float*)d_in[2];
    const float* ba    = (const float*)d_in[3];
    const float* lna_g = (const float*)d_in[4];
    const float* lna_b = (const float*)d_in[5];
    const float* Wt    = (const float*)d_in[6];
    const float* bt    = (const float*)d_in[7];
    const float* lnt_g = (const float*)d_in[8];
    const float* lnt_b = (const float*)d_in[9];
    const float* W1    = (const float*)d_in[10];
    const float* as1   = (const float*)d_in[11];
    const float* ad1   = (const float*)d_in[12];
    const float* b1    = (const float*)d_in[13];
    const float* W2    = (const float*)d_in[14];
    const float* as2   = (const float*)d_in[15];
    const float* ad2   = (const float*)d_in[16];
    const float* b2    = (const float*)d_in[17];
    const float* Wf    = (const float*)d_in[18];
    const float* bf    = (const float*)d_in[19];
    const float* lnf_g = (const float*)d_in[20];
    const float* lnf_b = (const float*)d_in[21];
    float* out = (float*)d_out;

    float *Za, *Zt, *W2T, *Wc, *bc, *xp2;
    __nv_bfloat16 *Aa3, *At3, *H3, *Wa3, *Wt3, *W13, *Wc3;
    cudaGetSymbolAddress((void**)&Za,  g_Za);
    cudaGetSymbolAddress((void**)&Zt,  g_Zt);
    cudaGetSymbolAddress((void**)&W2T, g_W2T);
    cudaGetSymbolAddress((void**)&Wc,  g_Wc);
    cudaGetSymbolAddress((void**)&bc,  g_bc);
    cudaGetSymbolAddress((void**)&xp2, g_xp2);
    cudaGetSymbolAddress((void**)&Aa3, g_Aa3);
    cudaGetSymbolAddress((void**)&At3, g_At3);
    cudaGetSymbolAddress((void**)&H3,  g_H3);
    cudaGetSymbolAddress((void**)&Wa3, g_Wa3);
    cudaGetSymbolAddress((void**)&Wt3, g_Wt3);
    cudaGetSymbolAddress((void**)&W13, g_W13);
    cudaGetSymbolAddress((void**)&Wc3, g_Wc3);

    cudaFuncSetAttribute(mma_gemm, cudaFuncAttributeMaxDynamicSharedMemorySize, MM_SMEM);

    // weight prep: Wc = Wf @ W2 (fold fc into gat2), bc = Wf@b2 + bf
    transpose_kernel<<<dim3(HD / 32, DD / 32), dim3(32, 8)>>>(W2, W2T);
    sgemm_nt<<<dim3(HD / 128, DD / 128), 256>>>(Wf, W2T, Wc, DD, HD, DD);
    bc_kernel<<<DD / 256, 256>>>(Wf, b2, bf, bc);
    convB3_kernel<<<(DD * DD / 4) / 256, 256>>>(Wa, Wa3, DD);
    convB3_kernel<<<(DD * DD / 4) / 256, 256>>>(Wt, Wt3, DD);
    convB3_kernel<<<(HD * DD / 4) / 256, 256>>>(W1, W13, DD);
    convB3_kernel<<<(DD * HD / 4) / 256, 256>>>(Wc, Wc3, HD);

    // inputs -> tripled bf16
    convA3_kernel<<<(NB * DD / 4) / 256, 256>>>(audio, Aa3, DD);
    convA3_kernel<<<(NB * DD / 4) / 256, 256>>>(text, At3, DD);

    // proj GEMMs + LN+relu -> tripled bf16 (overwrite Aa3/At3)
    mma_gemm<<<dim3(DD / BN, NB / BM), 256, MM_SMEM>>>(Aa3, Wa3, Za, NB, DD, K3A);
    ln3_kernel<<<NB, 256>>>(Za, ba, lna_g, lna_b, Aa3);
    mma_gemm<<<dim3(DD / BN, NB / BM), 256, MM_SMEM>>>(At3, Wt3, Zt, NB, DD, K3A);
    ln3_kernel<<<NB, 256>>>(Zt, bt, lnt_g, lnt_b, At3);

    // GAT1 linear
    mma_gemm<<<dim3(HD / BN, NB / BM), 256, MM_SMEM>>>(Aa3, W13, Za, NB, HD, K3A);
    mma_gemm<<<dim3(HD / BN, NB / BM), 256, MM_SMEM>>>(At3, W13, Zt, NB, HD, K3A);

    // pair-0 attention fixes + H build
    fixup1_kernel<<<1, 1024>>>(Za, Zt, as1, ad1);
    h3_kernel<<<NB, 512>>>(Za, Zt, b1, H3);
    fixup2a_kernel<<<8, 128>>>(Za, Zt, b1, W2, xp2);
    fixup2b_kernel<<<1, 1024>>>(xp2, as2, ad2, Za, Zt, b1, H3);

    // fused GAT2+fc GEMM, then final LN
    mma_gemm<<<dim3(DD / BN, NB / BM), 256, MM_SMEM>>>(H3, Wc3, out, NB, DD, K3H);
    ln_kernel<<<NB, 256>>>(out, bc, lnf_g, lnf_b, out);
}

// round 5
// speedup vs baseline: 3.3191x; 1.3154x over previous
#include <cuda_runtime.h>
#include <cuda_fp16.h>
#include <cstdint>
#include <cstddef>

#define NB 16384
#define DD 1024
#define HD 2048
#define K2A (2*DD)     // 2048
#define K2H (2*HD)     // 4096

// ---------------------------------------------------------------------------
// Scratch (device globals)
// ---------------------------------------------------------------------------
__device__ float g_Za[(size_t)NB * HD];
__device__ float g_Zt[(size_t)NB * HD];
__device__ float g_W2T[(size_t)HD * DD];
__device__ float g_Wc [(size_t)DD * HD];
__device__ float g_bc [DD];
__device__ float g_xp2[2 * DD];
__device__ __half g_Aa2[(size_t)NB * K2A];   // 64MB (audio2 then Xa2)
__device__ __half g_At2[(size_t)NB * K2A];   // 64MB
__device__ __half g_H2 [(size_t)NB * K2H];   // 128MB
__device__ __half g_Wa2[(size_t)DD * K2A];
__device__ __half g_Wt2[(size_t)DD * K2A];
__device__ __half g_W12[(size_t)HD * K2A];
__device__ __half g_Wc2[(size_t)DD * K2H];

__device__ __forceinline__ float lrelu_f(float v) { return v > 0.f ? v : 0.2f * v; }

// ---------------------------------------------------------------------------
// PTX helpers (sm_80-era only: cp.async, ldmatrix, mma.sync)
// ---------------------------------------------------------------------------
__device__ __forceinline__ uint32_t smem_u32(const void* p) {
    uint32_t a;
    asm("{ .reg .u64 t; cvta.to.shared.u64 t, %1; cvt.u32.u64 %0, t; }" : "=r"(a) : "l"(p));
    return a;
}
__device__ __forceinline__ void cp_async16(uint32_t s, const void* g) {
    asm volatile("cp.async.cg.shared.global [%0], [%1], 16;\n" :: "r"(s), "l"(g));
}
__device__ __forceinline__ uint32_t sw(uint32_t off) { return off ^ ((off >> 3) & 0x70); }

__device__ __forceinline__ void ldsm_x4(uint32_t (&r)[4], uint32_t addr) {
    asm volatile("ldmatrix.sync.aligned.m8n8.x4.shared.b16 {%0,%1,%2,%3}, [%4];"
        : "=r"(r[0]), "=r"(r[1]), "=r"(r[2]), "=r"(r[3]) : "r"(addr));
}
__device__ __forceinline__ void mma_f16(float (&c)[4], const uint32_t (&a)[4],
                                        uint32_t b0, uint32_t b1) {
    asm volatile("mma.sync.aligned.m16n8k16.row.col.f32.f16.f16.f32 "
        "{%0,%1,%2,%3}, {%4,%5,%6,%7}, {%8,%9}, {%0,%1,%2,%3};"
        : "+f"(c[0]), "+f"(c[1]), "+f"(c[2]), "+f"(c[3])
        : "r"(a[0]), "r"(a[1]), "r"(a[2]), "r"(a[3]), "r"(b0), "r"(b1));
}

// ---------------------------------------------------------------------------
// fp16 GEMM via mma.sync: C[M,N] = A2[M,K2] * B2[N,K2]^T (fp32 accum)
// CTA tile 128x128, BK=64, 3-stage cp.async pipeline, 256 threads (8 warps
// as 4(m) x 2(n), warp tile 32x64).
// ---------------------------------------------------------------------------
#define BM 128
#define BN 128
#define BK 64
#define NST 3
#define HTILE 16384                       // 128 rows * 128 bytes
#define STAGE_BYTES (2 * HTILE)
#define MM_SMEM (NST * STAGE_BYTES)       // 98304

__global__ void __launch_bounds__(256, 2) mma_gemm(
    const __half* __restrict__ A, const __half* __restrict__ B,
    float* __restrict__ C, int M, int N, int K2)
{
    extern __shared__ char smem[];
    const uint32_t sb = smem_u32(smem);
    const int tid = threadIdx.x;
    const int bm = blockIdx.y * BM;
    const int bn = blockIdx.x * BN;
    const int nk = K2 / BK;

    const int wid = tid >> 5, lane = tid & 31;
    const int wm = (wid & 3) * 32;
    const int wn = (wid >> 2) * 64;

    float acc[2][8][4];
#pragma unroll
    for (int i = 0; i < 2; i++)
#pragma unroll
        for (int j = 0; j < 8; j++)
#pragma unroll
            for (int k = 0; k < 4; k++) acc[i][j][k] = 0.f;

    auto load_stage = [&](int chunk, int slot) {
        const size_t kb = (size_t)chunk * BK;
        const uint32_t sA = sb + slot * STAGE_BYTES;
        const uint32_t sB = sA + HTILE;
#pragma unroll
        for (int i = 0; i < 4; i++) {
            const int c = tid + i * 256;
            const int row = c >> 3, kc = c & 7;
            cp_async16(sA + sw(row * 128 + kc * 16),
                       A + (size_t)(bm + row) * K2 + kb + kc * 8);
        }
#pragma unroll
        for (int i = 0; i < 4; i++) {
            const int c = tid + i * 256;
            const int row = c >> 3, kc = c & 7;
            cp_async16(sB + sw(row * 128 + kc * 16),
                       B + (size_t)(bn + row) * K2 + kb + kc * 8);
        }
        asm volatile("cp.async.commit_group;\n" ::: "memory");
    };

    load_stage(0, 0);
    load_stage(1, 1);

    for (int t = 0; t < nk; t++) {
        if (t + 2 < nk) asm volatile("cp.async.wait_group 1;\n" ::: "memory");
        else            asm volatile("cp.async.wait_group 0;\n" ::: "memory");
        __syncthreads();

        const uint32_t aS = sb + (t % NST) * STAGE_BYTES;
        const uint32_t bS = aS + HTILE;
#pragma unroll
        for (int ks = 0; ks < 4; ks++) {
            uint32_t af[2][4];
#pragma unroll
            for (int mf = 0; mf < 2; mf++) {
                const uint32_t row = wm + mf * 16 + (lane & 15);
                const uint32_t off = row * 128 + ks * 32 + ((lane >> 4) << 4);
                ldsm_x4(af[mf], aS + sw(off));
            }
            uint32_t bfr[8][2];
#pragma unroll
            for (int np = 0; np < 4; np++) {
                const uint32_t row = wn + np * 16 + ((lane >> 4) << 3) + (lane & 7);
                const uint32_t off = row * 128 + ks * 32 + (((lane >> 3) & 1) << 4);
                uint32_t r[4];
                ldsm_x4(r, bS + sw(off));
                bfr[2*np][0] = r[0]; bfr[2*np][1] = r[1];
                bfr[2*np+1][0] = r[2]; bfr[2*np+1][1] = r[3];
            }
#pragma unroll
            for (int mf = 0; mf < 2; mf++)
#pragma unroll
                for (int nf = 0; nf < 8; nf++)
                    mma_f16(acc[mf][nf], af[mf], bfr[nf][0], bfr[nf][1]);
        }

        if (t + 2 < nk) load_stage(t + 2, (t + 2) % NST);
    }

    // epilogue
    const int gid = lane >> 2, qid = lane & 3;
#pragma unroll
    for (int mf = 0; mf < 2; mf++) {
#pragma unroll
        for (int half_ = 0; half_ < 2; half_++) {
            const int row = bm + wm + mf * 16 + gid + half_ * 8;
            float* Cr = C + (size_t)row * N + bn + wn + qid * 2;
#pragma unroll
            for (int nf = 0; nf < 8; nf++) {
                float2 v = make_float2(acc[mf][nf][half_ * 2], acc[mf][nf][half_ * 2 + 1]);
                *(float2*)(Cr + nf * 8) = v;
            }
        }
    }
}

// ---------------------------------------------------------------------------
// fp32 -> fp16 hi/lo split helpers + conversion kernels
// ---------------------------------------------------------------------------
__device__ __forceinline__ void splitH(float a, float b, __half2& h, __half2& l) {
    const __half ha = __float2half_rn(a), hb = __float2half_rn(b);
    h = __halves2half2(ha, hb);
    l = __halves2half2(__float2half_rn(a - __half2float(ha)),
                       __float2half_rn(b - __half2float(hb)));
}

// activation layout: [hi | lo], out row stride 2K
__global__ void convA2_kernel(const float* __restrict__ in, __half* __restrict__ out, int K)
{
    const size_t idx = (size_t)blockIdx.x * blockDim.x + threadIdx.x;
    const int kq = (int)(idx % (K / 4)) * 4;
    const size_t m = idx / (K / 4);
    const float4 v = *(const float4*)(in + m * K + kq);
    __half2 h0, l0, h1, l1;
    splitH(v.x, v.y, h0, l0); splitH(v.z, v.w, h1, l1);
    __half* base = out + m * (size_t)(2 * K) + kq;
    *(__half2*)(base)     = h0; *(__half2*)(base + 2)     = h1;
    *(__half2*)(base + K) = l0; *(__half2*)(base + K + 2) = l1;
}

// weight layout: [h | h] duplicated, out row stride 2K
__global__ void convB2_kernel(const float* __restrict__ in, __half* __restrict__ out, int K)
{
    const size_t idx = (size_t)blockIdx.x * blockDim.x + threadIdx.x;
    const int kq = (int)(idx % (K / 4)) * 4;
    const size_t m = idx / (K / 4);
    const float4 v = *(const float4*)(in + m * K + kq);
    const __half2 h0 = __halves2half2(__float2half_rn(v.x), __float2half_rn(v.y));
    const __half2 h1 = __halves2half2(__float2half_rn(v.z), __float2half_rn(v.w));
    __half* base = out + m * (size_t)(2 * K) + kq;
    *(__half2*)(base)     = h0; *(__half2*)(base + 2)     = h1;
    *(__half2*)(base + K) = h0; *(__half2*)(base + K + 2) = h1;
}

// ---------------------------------------------------------------------------
// LayerNorm fp32 (final) and LN->relu->split fp16 (mid)
// ---------------------------------------------------------------------------
__global__ void __launch_bounds__(256) ln_kernel(
    const float* __restrict__ in, const float* __restrict__ bias,
    const float* __restrict__ gw, const float* __restrict__ bw,
    float* __restrict__ out)
{
    const size_t base = (size_t)blockIdx.x * DD;
    const int t = threadIdx.x;
    float4 v = *(const float4*)(in + base + t * 4);
    const float4 bb = *(const float4*)(bias + t * 4);
    v.x += bb.x; v.y += bb.y; v.z += bb.z; v.w += bb.w;
    float s1 = v.x + v.y + v.z + v.w;
    float s2 = v.x * v.x + v.y * v.y + v.z * v.z + v.w * v.w;
#pragma unroll
    for (int o = 16; o > 0; o >>= 1) {
        s1 += __shfl_xor_sync(0xffffffffu, s1, o);
        s2 += __shfl_xor_sync(0xffffffffu, s2, o);
    }
    __shared__ float sh1[8], sh2[8], stats[2];
    if ((t & 31) == 0) { sh1[t >> 5] = s1; sh2[t >> 5] = s2; }
    __syncthreads();
    if (t == 0) {
        float a = 0.f, b = 0.f;
#pragma unroll
        for (int i = 0; i < 8; i++) { a += sh1[i]; b += sh2[i]; }
        const float mean = a * (1.f / DD);
        stats[0] = mean;
        stats[1] = rsqrtf(b * (1.f / DD) - mean * mean + 1e-5f);
    }
    __syncthreads();
    const float mean = stats[0], rstd = stats[1];
    const float4 g4 = *(const float4*)(gw + t * 4);
    const float4 b4 = *(const float4*)(bw + t * 4);
    float4 r;
    r.x = (v.x - mean) * rstd * g4.x + b4.x;
    r.y = (v.y - mean) * rstd * g4.y + b4.y;
    r.z = (v.z - mean) * rstd * g4.z + b4.z;
    r.w = (v.w - mean) * rstd * g4.w + b4.w;
    *(float4*)(out + base + t * 4) = r;
}

__global__ void __launch_bounds__(256) ln2_kernel(
    const float* __restrict__ in, const float* __restrict__ bias,
    const float* __restrict__ gw, const float* __restrict__ bw,
    __half* __restrict__ out)  // [hi|lo], row stride 2*DD, with relu
{
    const size_t base = (size_t)blockIdx.x * DD;
    const int t = threadIdx.x;
    float4 v = *(const float4*)(in + base + t * 4);
    const float4 bb = *(const float4*)(bias + t * 4);
    v.x += bb.x; v.y += bb.y; v.z += bb.z; v.w += bb.w;
    float s1 = v.x + v.y + v.z + v.w;
    float s2 = v.x * v.x + v.y * v.y + v.z * v.z + v.w * v.w;
#pragma unroll
    for (int o = 16; o > 0; o >>= 1) {
        s1 += __shfl_xor_sync(0xffffffffu, s1, o);
        s2 += __shfl_xor_sync(0xffffffffu, s2, o);
    }
    __shared__ float sh1[8], sh2[8], stats[2];
    if ((t & 31) == 0) { sh1[t >> 5] = s1; sh2[t >> 5] = s2; }
    __syncthreads();
    if (t == 0) {
        float a = 0.f, b = 0.f;
#pragma unroll
        for (int i = 0; i < 8; i++) { a += sh1[i]; b += sh2[i]; }
        const float mean = a * (1.f / DD);
        stats[0] = mean;
        stats[1] = rsqrtf(b * (1.f / DD) - mean * mean + 1e-5f);
    }
    __syncthreads();
    const float mean = stats[0], rstd = stats[1];
    const float4 g4 = *(const float4*)(gw + t * 4);
    const float4 b4 = *(const float4*)(bw + t * 4);
    float4 r;
    r.x = fmaxf((v.x - mean) * rstd * g4.x + b4.x, 0.f);
    r.y = fmaxf((v.y - mean) * rstd * g4.y + b4.y, 0.f);
    r.z = fmaxf((v.z - mean) * rstd * g4.z + b4.z, 0.f);
    r.w = fmaxf((v.w - mean) * rstd * g4.w + b4.w, 0.f);
    __half2 h0, l0, h1, l1;
    splitH(r.x, r.y, h0, l0); splitH(r.z, r.w, h1, l1);
    __half* ob = out + (size_t)blockIdx.x * K2A + t * 4;
    *(__half2*)(ob)          = h0; *(__half2*)(ob + 2)          = h1;
    *(__half2*)(ob + DD)     = l0; *(__half2*)(ob + DD + 2)     = l1;
}

// H row = 0.5*(relu(Za+b1)+relu(Zt+b1)) -> split fp16 [hi|lo], stride 2*HD
__global__ void __launch_bounds__(512) h2_kernel(
    const float* __restrict__ Za, const float* __restrict__ Zt,
    const float* __restrict__ b1, __half* __restrict__ H2)
{
    const size_t base = (size_t)blockIdx.x * HD;
    const int j = threadIdx.x * 4;
    const float4 za = *(const float4*)(Za + base + j);
    const float4 zt = *(const float4*)(Zt + base + j);
    const float4 bb = *(const float4*)(b1 + j);
    float4 r;
    r.x = 0.5f * (fmaxf(za.x + bb.x, 0.f) + fmaxf(zt.x + bb.x, 0.f));
    r.y = 0.5f * (fmaxf(za.y + bb.y, 0.f) + fmaxf(zt.y + bb.y, 0.f));
    r.z = 0.5f * (fmaxf(za.z + bb.z, 0.f) + fmaxf(zt.z + bb.z, 0.f));
    r.w = 0.5f * (fmaxf(za.w + bb.w, 0.f) + fmaxf(zt.w + bb.w, 0.f));
    __half2 h0, l0, h1, l1;
    splitH(r.x, r.y, h0, l0); splitH(r.z, r.w, h1, l1);
    __half* ob = H2 + (size_t)blockIdx.x * K2H + j;
    *(__half2*)(ob)          = h0; *(__half2*)(ob + 2)          = h1;
    *(__half2*)(ob + HD)     = l0; *(__half2*)(ob + HD + 2)     = l1;
}

// ---------------------------------------------------------------------------
// fp32 SGEMM (for the small Wc = Wf @ W2 fold) + transpose + bc
// ---------------------------------------------------------------------------
__global__ void __launch_bounds__(256) sgemm_nt(
    const float* __restrict__ A, const float* __restrict__ B,
    float* __restrict__ C, int M, int N, int K)
{
    __shared__ float As[2][8][128];
    __shared__ float Bs[2][8][128];
    const int tid = threadIdx.x;
    const int bm = blockIdx.y * 128, bn = blockIdx.x * 128;
    const int lrow = tid >> 1, lk = (tid & 1) << 2;
    const float* Ap = A + (size_t)(bm + lrow) * K + lk;
    const float* Bp = B + (size_t)(bn + lrow) * K + lk;
    const int w = tid >> 5, l = tid & 31;
    const int tm = (w & 3) * 32 + (l >> 3) * 8;
    const int tn = (w >> 2) * 64 + (l & 7) * 8;
    float acc[8][8];
#pragma unroll
    for (int i = 0; i < 8; i++)
#pragma unroll
        for (int j = 0; j < 8; j++) acc[i][j] = 0.f;
    float4 a4 = *(const float4*)Ap;
    float4 b4 = *(const float4*)Bp;
    As[0][lk+0][lrow] = a4.x; As[0][lk+1][lrow] = a4.y;
    As[0][lk+2][lrow] = a4.z; As[0][lk+3][lrow] = a4.w;
    Bs[0][lk+0][lrow] = b4.x; Bs[0][lk+1][lrow] = b4.y;
    Bs[0][lk+2][lrow] = b4.z; Bs[0][lk+3][lrow] = b4.w;
    __syncthreads();
    const int nk = K >> 3;
    int buf = 0;
    for (int t = 0; t < nk; t++) {
        if (t + 1 < nk) {
            a4 = *(const float4*)(Ap + (size_t)(t + 1) * 8);
            b4 = *(const float4*)(Bp + (size_t)(t + 1) * 8);
        }
#pragma unroll
        for (int kk = 0; kk < 8; kk++) {
            float a[8], b[8];
            *(float4*)(a)     = *(const float4*)&As[buf][kk][tm];
            *(float4*)(a + 4) = *(const float4*)&As[buf][kk][tm + 4];
            *(float4*)(b)     = *(const float4*)&Bs[buf][kk][tn];
            *(float4*)(b + 4) = *(const float4*)&Bs[buf][kk][tn + 4];
#pragma unroll
            for (int i = 0; i < 8; i++)
#pragma unroll
                for (int j = 0; j < 8; j++) acc[i][j] += a[i] * b[j];
        }
        if (t + 1 < nk) {
            const int nb = buf ^ 1;
            As[nb][lk+0][lrow] = a4.x; As[nb][lk+1][lrow] = a4.y;
            As[nb][lk+2][lrow] = a4.z; As[nb][lk+3][lrow] = a4.w;
            Bs[nb][lk+0][lrow] = b4.x; Bs[nb][lk+1][lrow] = b4.y;
            Bs[nb][lk+2][lrow] = b4.z; Bs[nb][lk+3][lrow] = b4.w;
        }
        __syncthreads();
        buf ^= 1;
    }
#pragma unroll
    for (int i = 0; i < 8; i++) {
        float* Cp = C + (size_t)(bm + tm + i) * N + bn + tn;
        *(float4*)(Cp)     = make_float4(acc[i][0], acc[i][1], acc[i][2], acc[i][3]);
        *(float4*)(Cp + 4) = make_float4(acc[i][4], acc[i][5], acc[i][6], acc[i][7]);
    }
}

__global__ void transpose_kernel(const float* __restrict__ in, float* __restrict__ out)
{
    __shared__ float tile[32][33];
    const int x = blockIdx.x * 32 + threadIdx.x;
    const int y0 = blockIdx.y * 32;
    for (int j = threadIdx.y; j < 32; j += 8)
        tile[j][threadIdx.x] = in[(size_t)(y0 + j) * HD + x];
    __syncthreads();
    const int ox = blockIdx.y * 32 + threadIdx.x;
    const int oy0 = blockIdx.x * 32;
    for (int j = threadIdx.y; j < 32; j += 8)
        out[(size_t)(oy0 + j) * DD + ox] = tile[threadIdx.x][j];
}

__global__ void bc_kernel(const float* __restrict__ Wf, const float* __restrict__ b2,
                          const float* __restrict__ bf, float* __restrict__ bc)
{
    const int i = blockIdx.x * 256 + threadIdx.x;
    float s = 0.f;
    for (int k = 0; k < DD; k++) s += Wf[(size_t)i * DD + k] * b2[k];
    bc[i] = s + bf[i];
}

// ---------------------------------------------------------------------------
// Pair-0 fixups (exact GAT attention for nodes 0<->1)
// ---------------------------------------------------------------------------
__global__ void __launch_bounds__(1024) fixup1_kernel(
    float* Za, float* Zt, const float* __restrict__ as1, const float* __restrict__ ad1)
{
    const int t = threadIdx.x;
    const int wid = t >> 5, lane = t & 31;
    __shared__ float red[32][8];
    __shared__ float coef[8];
    float za[2], zt[2], p[8];
#pragma unroll
    for (int h = 0; h < 2; h++) {
        const int j = h * DD + t;
        const float a = as1[j], d = ad1[j];
        za[h] = Za[j]; zt[h] = Zt[j];
        p[h*4+0] = za[h] * a; p[h*4+1] = za[h] * d;
        p[h*4+2] = zt[h] * a; p[h*4+3] = zt[h] * d;
    }
#pragma unroll
    for (int i = 0; i < 8; i++)
#pragma unroll
        for (int o = 16; o > 0; o >>= 1) p[i] += __shfl_xor_sync(0xffffffffu, p[i], o);
    if (lane == 0)
#pragma unroll
        for (int i = 0; i < 8; i++) red[wid][i] = p[i];
    __syncthreads();
    if (t == 0) {
        float S[8];
#pragma unroll
        for (int i = 0; i < 8; i++) {
            float s = 0.f;
            for (int wv = 0; wv < 32; wv++) s += red[wv][i];
            S[i] = s;
        }
        for (int h = 0; h < 2; h++) {
            const float s0 = S[h*4+0], d0 = S[h*4+1], s1 = S[h*4+2], d1 = S[h*4+3];
            const float e00 = lrelu_f(s0 + d0), e10 = lrelu_f(s1 + d0);
            const float m0 = fmaxf(e00, e10);
            const float q0 = expf(e00 - m0), q1 = expf(e10 - m0);
            coef[h*4+0] = q0 / (q0 + q1); coef[h*4+1] = q1 / (q0 + q1);
            const float e11 = lrelu_f(s1 + d1), e01 = lrelu_f(s0 + d1);
            const float m1 = fmaxf(e11, e01);
            const float r0 = expf(e11 - m1), r1 = expf(e01 - m1);
            coef[h*4+2] = r0 / (r0 + r1); coef[h*4+3] = r1 / (r0 + r1);
        }
    }
    __syncthreads();
#pragma unroll
    for (int h = 0; h < 2; h++) {
        const int j = h * DD + t;
        Za[j] = coef[h*4+0] * za[h] + coef[h*4+1] * zt[h];
        Zt[j] = coef[h*4+2] * zt[h] + coef[h*4+3] * za[h];
    }
}

__global__ void fixup2a_kernel(
    const float* __restrict__ Za, const float* __restrict__ Zt,
    const float* __restrict__ b1, const float* __restrict__ W2,
    float* __restrict__ xp2)
{
    const int i = blockIdx.x * 128 + threadIdx.x;
    float a0 = 0.f, a1 = 0.f;
    for (int j = 0; j < HD; j++) {
        const float g0 = fmaxf(Za[j] + b1[j], 0.f);
        const float g1 = fmaxf(Zt[j] + b1[j], 0.f);
        const float wv = W2[(size_t)i * HD + j];
        a0 += g0 * wv; a1 += g1 * wv;
    }
    xp2[i] = a0; xp2[DD + i] = a1;
}

__global__ void __launch_bounds__(1024) fixup2b_kernel(
    const float* __restrict__ xp2, const float* __restrict__ as2,
    const float* __restrict__ ad2, const float* __restrict__ Za,
    const float* __restrict__ Zt, const float* __restrict__ b1,
    __half* __restrict__ H2)   // rewrites row 0 ([hi|lo] layout)
{
    const int t = threadIdx.x;
    const int wid = t >> 5, lane = t & 31;
    __shared__ float red[32][4];
    __shared__ float cf[2];
    const float x0 = xp2[t], x1 = xp2[DD + t];
    const float a = as2[t], d = ad2[t];
    float p[4] = { x0 * a, x0 * d, x1 * a, x1 * d };
#pragma unroll
    for (int i = 0; i < 4; i++)
#pragma unroll
        for (int o = 16; o > 0; o >>= 1) p[i] += __shfl_xor_sync(0xffffffffu, p[i], o);
    if (lane == 0)
#pragma unroll
        for (int i = 0; i < 4; i++) red[wid][i] = p[i];
    __syncthreads();
    if (t == 0) {
        float S[4];
#pragma unroll
        for (int i = 0; i < 4; i++) {
            float s = 0.f;
            for (int wv = 0; wv < 32; wv++) s += red[wv][i];
            S[i] = s;
        }
        const float s0 = S[0], d0 = S[1], s1 = S[2], d1 = S[3];
        const float e00 = lrelu_f(s0 + d0), e10 = lrelu_f(s1 + d0);
        const float m0 = fmaxf(e00, e10);
        const float q0 = expf(e00 - m0), q1 = expf(e10 - m0);
        const float w0s = q0 / (q0 + q1), w0o = q1 / (q0 + q1);
        const float e11 = lrelu_f(s1 + d1), e01 = lrelu_f(s0 + d1);
        const float m1 = fmaxf(e11, e01);
        const float r0 = expf(e11 - m1), r1 = expf(e01 - m1);
        const float w1s = r0 / (r0 + r1), w1o = r1 / (r0 + r1);
        cf[0] = w0s + w1o;
        cf[1] = w0o + w1s;
    }
    __syncthreads();
#pragma unroll
    for (int h = 0; h < 2; h++) {
        const int j = h * DD + t;
        const float g0 = fmaxf(Za[j] + b1[j], 0.f);
        const float g1 = fmaxf(Zt[j] + b1[j], 0.f);
        const float hv = 0.5f * (cf[0] * g0 + cf[1] * g1);
        const __half hh = __float2half_rn(hv);
        const __half ll = __float2half_rn(hv - __half2float(hh));
        H2[j] = hh; H2[HD + j] = ll;
    }
}

// ---------------------------------------------------------------------------
// Launch
// ---------------------------------------------------------------------------
extern "C" void kernel_launch(void* const* d_in, const int* in_sizes, int n_in,
                              void* d_out, int out_size)
{
    const float* audio = (const float*)d_in[0];
    const float* text  = (const float*)d_in[1];
    const float* Wa    = (const float*)d_in[2];
    const float* ba    = (const float*)d_in[3];
    const float* lna_g = (const float*)d_in[4];
    const float* lna_b = (const float*)d_in[5];
    const float* Wt    = (const float*)d_in[6];
    const float* bt    = (const float*)d_in[7];
    const float* lnt_g = (const float*)d_in[8];
    const float* lnt_b = (const float*)d_in[9];
    const float* W1    = (const float*)d_in[10];
    const float* as1   = (const float*)d_in[11];
    const float* ad1   = (const float*)d_in[12];
    const float* b1    = (const float*)d_in[13];
    const float* W2    = (const float*)d_in[14];
    const float* as2   = (const float*)d_in[15];
    const float* ad2   = (const float*)d_in[16];
    const float* b2    = (const float*)d_in[17];
    const float* Wf    = (const float*)d_in[18];
    const float* bf    = (const float*)d_in[19];
    const float* lnf_g = (const float*)d_in[20];
    const float* lnf_b = (const float*)d_in[21];
    float* out = (float*)d_out;

    float *Za, *Zt, *W2T, *Wc, *bc, *xp2;
    __half *Aa2, *At2, *H2, *Wa2, *Wt2, *W12, *Wc2;
    cudaGetSymbolAddress((void**)&Za,  g_Za);
    cudaGetSymbolAddress((void**)&Zt,  g_Zt);
    cudaGetSymbolAddress((void**)&W2T, g_W2T);
    cudaGetSymbolAddress((void**)&Wc,  g_Wc);
    cudaGetSymbolAddress((void**)&bc,  g_bc);
    cudaGetSymbolAddress((void**)&xp2, g_xp2);
    cudaGetSymbolAddress((void**)&Aa2, g_Aa2);
    cudaGetSymbolAddress((void**)&At2, g_At2);
    cudaGetSymbolAddress((void**)&H2,  g_H2);
    cudaGetSymbolAddress((void**)&Wa2, g_Wa2);
    cudaGetSymbolAddress((void**)&Wt2, g_Wt2);
    cudaGetSymbolAddress((void**)&W12, g_W12);
    cudaGetSymbolAddress((void**)&Wc2, g_Wc2);

    cudaFuncSetAttribute(mma_gemm, cudaFuncAttributeMaxDynamicSharedMemorySize, MM_SMEM);

    // weight prep: Wc = Wf @ W2 (fold fc into gat2), bc = Wf@b2 + bf
    transpose_kernel<<<dim3(HD / 32, DD / 32), dim3(32, 8)>>>(W2, W2T);
    sgemm_nt<<<dim3(HD / 128, DD / 128), 256>>>(Wf, W2T, Wc, DD, HD, DD);
    bc_kernel<<<DD / 256, 256>>>(Wf, b2, bf, bc);
    convB2_kernel<<<(DD * DD / 4) / 256, 256>>>(Wa, Wa2, DD);
    convB2_kernel<<<(DD * DD / 4) / 256, 256>>>(Wt, Wt2, DD);
    convB2_kernel<<<(HD * DD / 4) / 256, 256>>>(W1, W12, DD);
    convB2_kernel<<<(DD * HD / 4) / 256, 256>>>(Wc, Wc2, HD);

    // inputs -> split fp16
    convA2_kernel<<<(NB * DD / 4) / 256, 256>>>(audio, Aa2, DD);
    convA2_kernel<<<(NB * DD / 4) / 256, 256>>>(text, At2, DD);

    // proj GEMMs + LN+relu -> split fp16 (overwrite Aa2/At2)
    mma_gemm<<<dim3(DD / BN, NB / BM), 256, MM_SMEM>>>(Aa2, Wa2, Za, NB, DD, K2A);
    ln2_kernel<<<NB, 256>>>(Za, ba, lna_g, lna_b, Aa2);
    mma_gemm<<<dim3(DD / BN, NB / BM), 256, MM_SMEM>>>(At2, Wt2, Zt, NB, DD, K2A);
    ln2_kernel<<<NB, 256>>>(Zt, bt, lnt_g, lnt_b, At2);

    // GAT1 linear
    mma_gemm<<<dim3(HD / BN, NB / BM), 256, MM_SMEM>>>(Aa2, W12, Za, NB, HD, K2A);
    mma_gemm<<<dim3(HD / BN, NB / BM), 256, MM_SMEM>>>(At2, W12, Zt, NB, HD, K2A);

    // pair-0 attention fixes + H build
    fixup1_kernel<<<1, 1024>>>(Za, Zt, as1, ad1);
    h2_kernel<<<NB, 512>>>(Za, Zt, b1, H2);
    fixup2a_kernel<<<8, 128>>>(Za, Zt, b1, W2, xp2);
    fixup2b_kernel<<<1, 1024>>>(xp2, as2, ad2, Za, Zt, b1, H2);

    // fused GAT2+fc GEMM, then final LN
    mma_gemm<<<dim3(DD / BN, NB / BM), 256, MM_SMEM>>>(H2, Wc2, out, NB, DD, K2H);
    ln_kernel<<<NB, 256>>>(out, bc, lnf_g, lnf_b, out);
}